// round 1
// baseline (speedup 1.0000x reference)
#include <cuda_runtime.h>
#include <cuda_bf16.h>

#define B_  8
#define C_  64
#define H_  128
#define W_  128
#define O_  64
#define HW_ (H_*W_)
#define K2_ 9

// Scratch (device globals; no allocation allowed)
__device__ float g_xt[B_*HW_*C_];          // x transposed to [b][h][w][c]
__device__ float g_off[B_*2*K2_*HW_];      // offsets planar [b][j=0..17][h][w]
__device__ float g_wr[K2_*C_*O_];          // weights reordered [(k*64+c)][o]

__device__ __forceinline__ unsigned long long ffma2(unsigned long long a,
                                                    unsigned long long b,
                                                    unsigned long long c) {
    unsigned long long d;
    asm("fma.rn.f32x2 %0, %1, %2, %3;" : "=l"(d) : "l"(a), "l"(b), "l"(c));
    return d;
}
__device__ __forceinline__ unsigned long long pack2(float x, float y) {
    unsigned long long r;
    asm("mov.b64 %0, {%1, %2};" : "=l"(r) : "f"(x), "f"(y));
    return r;
}

// ---------------------------------------------------------------------------
// Kernel 1: NCHW -> NHWC transpose of x (per batch: [64][16384] -> [16384][64])
// ---------------------------------------------------------------------------
__global__ void k_transpose(const float* __restrict__ x) {
    __shared__ float tile[32][33];
    int b  = blockIdx.z;
    int c0 = blockIdx.y * 32;
    int p0 = blockIdx.x * 32;
    int tx = threadIdx.x, ty = threadIdx.y;
    const float* xb = x + (size_t)b * C_ * HW_;
#pragma unroll
    for (int i = 0; i < 32; i += 8)
        tile[ty + i][tx] = xb[(size_t)(c0 + ty + i) * HW_ + p0 + tx];
    __syncthreads();
    float* xtb = g_xt + (size_t)b * HW_ * C_;
#pragma unroll
    for (int i = 0; i < 32; i += 8)
        xtb[(size_t)(p0 + ty + i) * C_ + c0 + tx] = tile[tx][ty + i];
}

// ---------------------------------------------------------------------------
// Kernel 2: offsets  off[b,j,h,w] = sum_c x[b,c,h,w] * w_off[j,c] + b_off[j]
// ---------------------------------------------------------------------------
__global__ void k_offsets(const float* __restrict__ x,
                          const float* __restrict__ w_off,
                          const float* __restrict__ b_off) {
    __shared__ float sw[18 * 64];
    __shared__ float sb[18];
    int t = threadIdx.x;
    for (int i = t; i < 18 * 64; i += 256) sw[i] = w_off[i];
    if (t < 18) sb[t] = b_off[t];
    __syncthreads();

    int idx = blockIdx.x * 256 + t;      // over B*HW = 131072
    int b   = idx >> 14;
    int hw  = idx & (HW_ - 1);

    float acc[18];
#pragma unroll
    for (int j = 0; j < 18; j++) acc[j] = sb[j];

    const float* xp = x + (size_t)b * C_ * HW_ + hw;
#pragma unroll 4
    for (int c = 0; c < 64; c++) {
        float v = __ldg(xp + (size_t)c * HW_);
#pragma unroll
        for (int j = 0; j < 18; j++) acc[j] = fmaf(v, sw[j * 64 + c], acc[j]);
    }
    float* op = g_off + (size_t)b * 18 * HW_ + hw;
#pragma unroll
    for (int j = 0; j < 18; j++) op[(size_t)j * HW_] = acc[j];
}

// ---------------------------------------------------------------------------
// Kernel 3: reorder weight (O,C,3,3) -> g_wr[(k*64+c)*64+o]
// ---------------------------------------------------------------------------
__global__ void k_reorder_w(const float* __restrict__ w) {
    int i = blockIdx.x * 256 + threadIdx.x;
    if (i < K2_ * C_ * O_) {
        int o  = i & 63;
        int kc = i >> 6;
        int c  = kc & 63;
        int k  = kc >> 6;
        g_wr[i] = w[((size_t)o * 64 + c) * 9 + k];
    }
}

// ---------------------------------------------------------------------------
// Kernel 4: main deformable conv.
// One CTA per (b, h): 128 output pixels (full row). 256 threads.
// k-slab loop: sample 128x64 values into smem, then FFMA2 GEMM-accumulate.
// ---------------------------------------------------------------------------
#define SROW 68   // padded smem row (floats) for s_sm: 128B-aligned rows, low conflicts

__global__ void __launch_bounds__(256, 3) k_main(float* __restrict__ out) {
    extern __shared__ float smem[];
    float* s_s   = smem;                    // [128][SROW]  sampled values, c-minor
    float* s_w   = smem + 128 * SROW;       // [64][64]     weight slab for current k
    float* s_off = s_w + 64 * 64;           // [18][128]    offsets for this row

    int t   = threadIdx.x;
    int blk = blockIdx.x;                   // 0..1023
    int h   = blk & 127;
    int b   = blk >> 7;

    // stage offsets for this row (coalesced)
    {
        const float* op = g_off + (size_t)b * 18 * HW_ + (size_t)h * W_;
        for (int i = t; i < 18 * 128; i += 256) {
            int j = i >> 7, w = i & 127;
            s_off[i] = op[(size_t)j * HW_ + w];
        }
    }

    // persistent packed accumulators: 32 outputs (o = oh*32 .. +31) for pixel p
    unsigned long long acc[16];
#pragma unroll
    for (int i = 0; i < 16; i++) acc[i] = 0ULL;

    const int pa_cq = t & 15;    // float4 channel chunk 0..15
    const int pa_p0 = t >> 4;    // 0..15 (pixel within pass)
    const int pb_p  = t & 127;   // pixel for phase B
    const int pb_oh = t >> 7;    // output half 0/1

    const float* xtb = g_xt + (size_t)b * HW_ * C_;

    __syncthreads();

    for (int k = 0; k < 9; k++) {
        __syncthreads();   // previous phase B finished with s_s / s_w

        // stage weight slab for this k: 4096 floats
        {
            const float4* wsrc = (const float4*)(g_wr + (size_t)k * 4096);
            float4*       wdst = (float4*)s_w;
#pragma unroll
            for (int i = 0; i < 4; i++)
                wdst[t + i * 256] = __ldg(wsrc + t + i * 256);
        }

        int kh = k / 3;
        int kw = k - kh * 3;

        // ---- Phase A: bilinear sampling, 8 passes x 16 pixels ----
#pragma unroll 2
        for (int pass = 0; pass < 8; pass++) {
            int p = pass * 16 + pa_p0;
            float py = (float)(h - 1 + kh) + s_off[(2 * k) * 128 + p];
            float px = (float)(p - 1 + kw) + s_off[(2 * k + 1) * 128 + p];
            float fy0 = floorf(py), fx0 = floorf(px);
            float wy1 = py - fy0,   wx1 = px - fx0;
            float wy0 = 1.0f - wy1, wx0 = 1.0f - wx1;
            int y0 = (int)fy0, x0 = (int)fx0;
            int y1 = y0 + 1,   x1 = x0 + 1;
            bool vy0 = (unsigned)y0 < (unsigned)H_;
            bool vy1 = (unsigned)y1 < (unsigned)H_;
            bool vx0 = (unsigned)x0 < (unsigned)W_;
            bool vx1 = (unsigned)x1 < (unsigned)W_;
            int y0c = min(max(y0, 0), H_ - 1), y1c = min(max(y1, 0), H_ - 1);
            int x0c = min(max(x0, 0), W_ - 1), x1c = min(max(x1, 0), W_ - 1);
            float w00 = (vy0 && vx0) ? wy0 * wx0 : 0.0f;
            float w01 = (vy0 && vx1) ? wy0 * wx1 : 0.0f;
            float w10 = (vy1 && vx0) ? wy1 * wx0 : 0.0f;
            float w11 = (vy1 && vx1) ? wy1 * wx1 : 0.0f;

            const float4* r00 = (const float4*)(xtb + (size_t)(y0c * W_ + x0c) * C_) + pa_cq;
            const float4* r01 = (const float4*)(xtb + (size_t)(y0c * W_ + x1c) * C_) + pa_cq;
            const float4* r10 = (const float4*)(xtb + (size_t)(y1c * W_ + x0c) * C_) + pa_cq;
            const float4* r11 = (const float4*)(xtb + (size_t)(y1c * W_ + x1c) * C_) + pa_cq;
            float4 va = __ldg(r00);
            float4 vb = __ldg(r01);
            float4 vc = __ldg(r10);
            float4 vd = __ldg(r11);

            float4 s;
            s.x = w00 * va.x + w01 * vb.x + w10 * vc.x + w11 * vd.x;
            s.y = w00 * va.y + w01 * vb.y + w10 * vc.y + w11 * vd.y;
            s.z = w00 * va.z + w01 * vb.z + w10 * vc.z + w11 * vd.z;
            s.w = w00 * va.w + w01 * vb.w + w10 * vc.w + w11 * vd.w;

            *(float4*)(s_s + p * SROW + pa_cq * 4) = s;
        }
        __syncthreads();

        // ---- Phase B: acc[o] += s[c] * w[c][o], packed f32x2 ----
        {
            const float* srow = s_s + pb_p * SROW;
#pragma unroll
            for (int ci4 = 0; ci4 < 16; ci4++) {
                float4 sv = *(const float4*)(srow + ci4 * 4);
                float svf[4] = {sv.x, sv.y, sv.z, sv.w};
#pragma unroll
                for (int u = 0; u < 4; u++) {
                    int c = ci4 * 4 + u;
                    unsigned long long sc2 = pack2(svf[u], svf[u]);
                    const ulonglong2* wp =
                        (const ulonglong2*)(s_w + c * 64 + pb_oh * 32);
#pragma unroll
                    for (int j = 0; j < 8; j++) {
                        ulonglong2 w2 = wp[j];
                        acc[2 * j]     = ffma2(sc2, w2.x, acc[2 * j]);
                        acc[2 * j + 1] = ffma2(sc2, w2.y, acc[2 * j + 1]);
                    }
                }
            }
        }
    }

    // write out: out[b][o][h][w], o = pb_oh*32 + 2j(+1), w = pb_p (coalesced)
    {
        float* ob = out + ((size_t)b * O_ + pb_oh * 32) * HW_ + (size_t)h * W_ + pb_p;
#pragma unroll
        for (int j = 0; j < 16; j++) {
            float lo = __uint_as_float((unsigned)(acc[j] & 0xffffffffULL));
            float hi = __uint_as_float((unsigned)(acc[j] >> 32));
            ob[(size_t)(2 * j) * HW_]     = lo;
            ob[(size_t)(2 * j + 1) * HW_] = hi;
        }
    }
}

// ---------------------------------------------------------------------------
extern "C" void kernel_launch(void* const* d_in, const int* in_sizes, int n_in,
                              void* d_out, int out_size) {
    const float* x     = (const float*)d_in[0];   // (8,64,128,128)
    const float* wght  = (const float*)d_in[1];   // (64,64,3,3)
    const float* w_off = (const float*)d_in[2];   // (18,64)
    const float* b_off = (const float*)d_in[3];   // (18,)
    float* out = (float*)d_out;                   // (8,64,128,128)

    k_transpose<<<dim3(HW_ / 32, C_ / 32, B_), dim3(32, 8)>>>(x);
    k_offsets<<<(B_ * HW_) / 256, 256>>>(x, w_off, b_off);
    k_reorder_w<<<(K2_ * C_ * O_ + 255) / 256, 256>>>(wght);

    const int smem_bytes = (128 * SROW + 64 * 64 + 18 * 128) * sizeof(float);
    cudaFuncSetAttribute(k_main, cudaFuncAttributeMaxDynamicSharedMemorySize,
                         smem_bytes);
    k_main<<<B_ * H_, 256, smem_bytes>>>(out);
}

// round 2
// speedup vs baseline: 1.4244x; 1.4244x over previous
#include <cuda_runtime.h>
#include <cuda_bf16.h>

#define B_  8
#define C_  64
#define H_  128
#define W_  128
#define O_  64
#define HW_ (H_*W_)
#define K2_ 9

// Scratch (device globals; no allocation allowed)
__device__ float g_xt[B_*HW_*C_];          // x transposed to [b][h][w][c]
__device__ float g_off[B_*2*K2_*HW_];      // offsets planar [b][j=0..17][h][w]
__device__ float g_wr[K2_*C_*O_];          // weights reordered [(k*64+c)][o]

__device__ __forceinline__ unsigned long long ffma2(unsigned long long a,
                                                    unsigned long long b,
                                                    unsigned long long c) {
    unsigned long long d;
    asm("fma.rn.f32x2 %0, %1, %2, %3;" : "=l"(d) : "l"(a), "l"(b), "l"(c));
    return d;
}
__device__ __forceinline__ unsigned long long pack2(float x, float y) {
    unsigned long long r;
    asm("mov.b64 %0, {%1, %2};" : "=l"(r) : "f"(x), "f"(y));
    return r;
}

// ---------------------------------------------------------------------------
// Kernel 1: NCHW -> NHWC transpose of x (per batch: [64][16384] -> [16384][64])
// ---------------------------------------------------------------------------
__global__ void k_transpose(const float* __restrict__ x) {
    __shared__ float tile[32][33];
    int b  = blockIdx.z;
    int c0 = blockIdx.y * 32;
    int p0 = blockIdx.x * 32;
    int tx = threadIdx.x, ty = threadIdx.y;
    const float* xb = x + (size_t)b * C_ * HW_;
#pragma unroll
    for (int i = 0; i < 32; i += 8)
        tile[ty + i][tx] = xb[(size_t)(c0 + ty + i) * HW_ + p0 + tx];
    __syncthreads();
    float* xtb = g_xt + (size_t)b * HW_ * C_;
#pragma unroll
    for (int i = 0; i < 32; i += 8)
        xtb[(size_t)(p0 + ty + i) * C_ + c0 + tx] = tile[tx][ty + i];
}

// ---------------------------------------------------------------------------
// Kernel 2: offsets  off[b,j,h,w] = sum_c x[b,c,h,w] * w_off[j,c] + b_off[j]
// ---------------------------------------------------------------------------
__global__ void k_offsets(const float* __restrict__ x,
                          const float* __restrict__ w_off,
                          const float* __restrict__ b_off) {
    __shared__ float sw[18 * 64];
    __shared__ float sb[18];
    int t = threadIdx.x;
    for (int i = t; i < 18 * 64; i += 256) sw[i] = w_off[i];
    if (t < 18) sb[t] = b_off[t];
    __syncthreads();

    int idx = blockIdx.x * 256 + t;      // over B*HW = 131072
    int b   = idx >> 14;
    int hw  = idx & (HW_ - 1);

    float acc[18];
#pragma unroll
    for (int j = 0; j < 18; j++) acc[j] = sb[j];

    const float* xp = x + (size_t)b * C_ * HW_ + hw;
#pragma unroll 4
    for (int c = 0; c < 64; c++) {
        float v = __ldg(xp + (size_t)c * HW_);
#pragma unroll
        for (int j = 0; j < 18; j++) acc[j] = fmaf(v, sw[j * 64 + c], acc[j]);
    }
    float* op = g_off + (size_t)b * 18 * HW_ + hw;
#pragma unroll
    for (int j = 0; j < 18; j++) op[(size_t)j * HW_] = acc[j];
}

// ---------------------------------------------------------------------------
// Kernel 3: reorder weight (O,C,3,3) -> g_wr[(k*64+c)*64+o]
// ---------------------------------------------------------------------------
__global__ void k_reorder_w(const float* __restrict__ w) {
    int i = blockIdx.x * 256 + threadIdx.x;
    if (i < K2_ * C_ * O_) {
        int o  = i & 63;
        int kc = i >> 6;
        int c  = kc & 63;
        int k  = kc >> 6;
        g_wr[i] = w[((size_t)o * 64 + c) * 9 + k];
    }
}

// ---------------------------------------------------------------------------
// Kernel 4: main deformable conv.
// One CTA per (b, h): 128 output pixels (full row). 256 threads.
// Phase A: sample 128x64 values into smem (k-slab).
// Phase B: warp w owns outputs [w*8, w*8+8); lane owns pixels lane+{0,32,64,96}.
//          Per channel: 2 broadcast LDS.128 (weights) + 1 LDS.128 (samples),
//          16 FFMA2. 2.75x fewer LDS than round-1 layout.
// ---------------------------------------------------------------------------
#define SROW 68   // padded smem row (floats): stride 68 -> conflict-free LDS.128

__global__ void __launch_bounds__(256, 3) k_main(float* __restrict__ out) {
    extern __shared__ float smem[];
    float* s_s   = smem;                    // [128][SROW]  sampled values, c-minor
    float* s_w   = smem + 128 * SROW;       // [64][64]     weight slab for current k
    float* s_off = s_w + 64 * 64;           // [18][128]    offsets for this row

    int t   = threadIdx.x;
    int blk = blockIdx.x;                   // 0..1023
    int h   = blk & 127;
    int b   = blk >> 7;

    // stage offsets for this row (coalesced)
    {
        const float* op = g_off + (size_t)b * 18 * HW_ + (size_t)h * W_;
        for (int i = t; i < 18 * 128; i += 256) {
            int j = i >> 7, w = i & 127;
            s_off[i] = op[(size_t)j * HW_ + w];
        }
    }

    // Phase-B mapping
    const int lane = t & 31;
    const int og   = t >> 5;      // warp id = output group: o in [og*8, og*8+8)

    // acc[i*4+j]: pixel px=lane+32*i, output pair o=(og*8+2j, og*8+2j+1)
    unsigned long long acc[16];
#pragma unroll
    for (int i = 0; i < 16; i++) acc[i] = 0ULL;

    // Phase-A mapping
    const int pa_cq = t & 15;    // float4 channel chunk 0..15
    const int pa_p0 = t >> 4;    // 0..15 (pixel within pass)

    const float* xtb = g_xt + (size_t)b * HW_ * C_;

    __syncthreads();

    for (int k = 0; k < 9; k++) {
        __syncthreads();   // previous phase B finished with s_s / s_w

        // stage weight slab for this k: 4096 floats
        {
            const float4* wsrc = (const float4*)(g_wr + (size_t)k * 4096);
            float4*       wdst = (float4*)s_w;
#pragma unroll
            for (int i = 0; i < 4; i++)
                wdst[t + i * 256] = __ldg(wsrc + t + i * 256);
        }

        int kh = k / 3;
        int kw = k - kh * 3;

        // ---- Phase A: bilinear sampling, 8 passes x 16 pixels ----
#pragma unroll 2
        for (int pass = 0; pass < 8; pass++) {
            int p = pass * 16 + pa_p0;
            float py = (float)(h - 1 + kh) + s_off[(2 * k) * 128 + p];
            float px = (float)(p - 1 + kw) + s_off[(2 * k + 1) * 128 + p];
            float fy0 = floorf(py), fx0 = floorf(px);
            float wy1 = py - fy0,   wx1 = px - fx0;
            float wy0 = 1.0f - wy1, wx0 = 1.0f - wx1;
            int y0 = (int)fy0, x0 = (int)fx0;
            int y1 = y0 + 1,   x1 = x0 + 1;
            bool vy0 = (unsigned)y0 < (unsigned)H_;
            bool vy1 = (unsigned)y1 < (unsigned)H_;
            bool vx0 = (unsigned)x0 < (unsigned)W_;
            bool vx1 = (unsigned)x1 < (unsigned)W_;
            int y0c = min(max(y0, 0), H_ - 1), y1c = min(max(y1, 0), H_ - 1);
            int x0c = min(max(x0, 0), W_ - 1), x1c = min(max(x1, 0), W_ - 1);
            float w00 = (vy0 && vx0) ? wy0 * wx0 : 0.0f;
            float w01 = (vy0 && vx1) ? wy0 * wx1 : 0.0f;
            float w10 = (vy1 && vx0) ? wy1 * wx0 : 0.0f;
            float w11 = (vy1 && vx1) ? wy1 * wx1 : 0.0f;

            const float4* r00 = (const float4*)(xtb + (size_t)(y0c * W_ + x0c) * C_) + pa_cq;
            const float4* r01 = (const float4*)(xtb + (size_t)(y0c * W_ + x1c) * C_) + pa_cq;
            const float4* r10 = (const float4*)(xtb + (size_t)(y1c * W_ + x0c) * C_) + pa_cq;
            const float4* r11 = (const float4*)(xtb + (size_t)(y1c * W_ + x1c) * C_) + pa_cq;
            float4 va = __ldg(r00);
            float4 vb = __ldg(r01);
            float4 vc = __ldg(r10);
            float4 vd = __ldg(r11);

            float4 s;
            s.x = w00 * va.x + w01 * vb.x + w10 * vc.x + w11 * vd.x;
            s.y = w00 * va.y + w01 * vb.y + w10 * vc.y + w11 * vd.y;
            s.z = w00 * va.z + w01 * vb.z + w10 * vc.z + w11 * vd.z;
            s.w = w00 * va.w + w01 * vb.w + w10 * vc.w + w11 * vd.w;

            *(float4*)(s_s + p * SROW + pa_cq * 4) = s;
        }
        __syncthreads();

        // ---- Phase B: acc[px][o] += s[px][c] * w[c][o], packed f32x2 ----
        {
            const float* wcol = s_w + og * 8;
#pragma unroll
            for (int c4 = 0; c4 < 16; c4++) {
                // sample values: 4 pixels x 4 channels
                float4 sv[4];
#pragma unroll
                for (int i = 0; i < 4; i++)
                    sv[i] = *(const float4*)(s_s + (lane + 32 * i) * SROW + c4 * 4);
#pragma unroll
                for (int u = 0; u < 4; u++) {
                    int c = c4 * 4 + u;
                    // 8 weights for this warp's output group (broadcast)
                    ulonglong2 wa = *(const ulonglong2*)(wcol + c * 64);
                    ulonglong2 wb = *(const ulonglong2*)(wcol + c * 64 + 4);
#pragma unroll
                    for (int i = 0; i < 4; i++) {
                        float sf = (u == 0) ? sv[i].x : (u == 1) ? sv[i].y
                                 : (u == 2) ? sv[i].z : sv[i].w;
                        unsigned long long sc2 = pack2(sf, sf);
                        acc[i * 4 + 0] = ffma2(sc2, wa.x, acc[i * 4 + 0]);
                        acc[i * 4 + 1] = ffma2(sc2, wa.y, acc[i * 4 + 1]);
                        acc[i * 4 + 2] = ffma2(sc2, wb.x, acc[i * 4 + 2]);
                        acc[i * 4 + 3] = ffma2(sc2, wb.y, acc[i * 4 + 3]);
                    }
                }
            }
        }
    }

    // write out: out[b][og*8 + 2j(+1)][h][lane + 32i]  (fully coalesced STG.32)
    {
        float* ob = out + ((size_t)b * O_ + og * 8) * HW_ + (size_t)h * W_ + lane;
#pragma unroll
        for (int i = 0; i < 4; i++) {
#pragma unroll
            for (int j = 0; j < 4; j++) {
                unsigned long long a = acc[i * 4 + j];
                float lo = __uint_as_float((unsigned)(a & 0xffffffffULL));
                float hi = __uint_as_float((unsigned)(a >> 32));
                ob[(size_t)(2 * j) * HW_ + 32 * i]     = lo;
                ob[(size_t)(2 * j + 1) * HW_ + 32 * i] = hi;
            }
        }
    }
}

// ---------------------------------------------------------------------------
extern "C" void kernel_launch(void* const* d_in, const int* in_sizes, int n_in,
                              void* d_out, int out_size) {
    const float* x     = (const float*)d_in[0];   // (8,64,128,128)
    const float* wght  = (const float*)d_in[1];   // (64,64,3,3)
    const float* w_off = (const float*)d_in[2];   // (18,64)
    const float* b_off = (const float*)d_in[3];   // (18,)
    float* out = (float*)d_out;                   // (8,64,128,128)

    k_transpose<<<dim3(HW_ / 32, C_ / 32, B_), dim3(32, 8)>>>(x);
    k_offsets<<<(B_ * HW_) / 256, 256>>>(x, w_off, b_off);
    k_reorder_w<<<(K2_ * C_ * O_ + 255) / 256, 256>>>(wght);

    const int smem_bytes = (128 * SROW + 64 * 64 + 18 * 128) * sizeof(float);
    cudaFuncSetAttribute(k_main, cudaFuncAttributeMaxDynamicSharedMemorySize,
                         smem_bytes);
    k_main<<<B_ * H_, 256, smem_bytes>>>(out);
}

// round 4
// speedup vs baseline: 1.7853x; 1.2534x over previous
#include <cuda_runtime.h>
#include <cuda_bf16.h>
#include <cstdint>

#define B_  8
#define C_  64
#define H_  128
#define W_  128
#define O_  64
#define HW_ (H_*W_)
#define K2_ 9

// Scratch (device globals; no allocation allowed)
__device__ float g_xt[B_*HW_*C_];              // x transposed to [b][h][w][c]
__device__ float g_off[B_*2*K2_*HW_];          // offsets planar [b][j][h][w]
__device__ __nv_bfloat16 g_wbh[K2_*4096];      // weight hi, swizzled [k][o(64) x c(64)]
__device__ __nv_bfloat16 g_wbl[K2_*4096];      // weight lo

// ---------------------------------------------------------------------------
__device__ __forceinline__ uint32_t smem_u32(const void* p) {
    uint32_t a;
    asm("{ .reg .u64 t; cvta.to.shared.u64 t, %1; cvt.u32.u64 %0, t; }"
        : "=r"(a) : "l"(p));
    return a;
}
__device__ __forceinline__ uint32_t cvt2bf(float hi, float lo) {
    uint32_t r;
    asm("cvt.rn.bf16x2.f32 %0, %1, %2;" : "=r"(r) : "f"(hi), "f"(lo));
    return r;
}
#define LDMX4(r, addr)                                                       \
    asm volatile("ldmatrix.sync.aligned.m8n8.x4.shared.b16 {%0,%1,%2,%3}, [%4];" \
        : "=r"((r)[0]), "=r"((r)[1]), "=r"((r)[2]), "=r"((r)[3]) : "r"(addr))
#define MMA16816(d, a, b0, b1)                                               \
    asm volatile("mma.sync.aligned.m16n8k16.row.col.f32.bf16.bf16.f32 "      \
        "{%0,%1,%2,%3}, {%4,%5,%6,%7}, {%8,%9}, {%0,%1,%2,%3};"              \
        : "+f"((d)[0]), "+f"((d)[1]), "+f"((d)[2]), "+f"((d)[3])             \
        : "r"((a)[0]), "r"((a)[1]), "r"((a)[2]), "r"((a)[3]),                \
          "r"(b0), "r"(b1))

// ---------------------------------------------------------------------------
// Kernel 1: NCHW -> NHWC transpose of x
// ---------------------------------------------------------------------------
__global__ void k_transpose(const float* __restrict__ x) {
    __shared__ float tile[32][33];
    int b  = blockIdx.z;
    int c0 = blockIdx.y * 32;
    int p0 = blockIdx.x * 32;
    int tx = threadIdx.x, ty = threadIdx.y;
    const float* xb = x + (size_t)b * C_ * HW_;
#pragma unroll
    for (int i = 0; i < 32; i += 8)
        tile[ty + i][tx] = xb[(size_t)(c0 + ty + i) * HW_ + p0 + tx];
    __syncthreads();
    float* xtb = g_xt + (size_t)b * HW_ * C_;
#pragma unroll
    for (int i = 0; i < 32; i += 8)
        xtb[(size_t)(p0 + ty + i) * C_ + c0 + tx] = tile[tx][ty + i];
}

// ---------------------------------------------------------------------------
// Kernel 2: offsets  off[b,j,h,w] = sum_c x[b,c,h,w] * w_off[j,c] + b_off[j]
// ---------------------------------------------------------------------------
__global__ void k_offsets(const float* __restrict__ x,
                          const float* __restrict__ w_off,
                          const float* __restrict__ b_off) {
    __shared__ float sw[18 * 64];
    __shared__ float sb[18];
    int t = threadIdx.x;
    for (int i = t; i < 18 * 64; i += 256) sw[i] = w_off[i];
    if (t < 18) sb[t] = b_off[t];
    __syncthreads();

    int idx = blockIdx.x * 256 + t;
    int b   = idx >> 14;
    int hw  = idx & (HW_ - 1);

    float acc[18];
#pragma unroll
    for (int j = 0; j < 18; j++) acc[j] = sb[j];

    const float* xp = x + (size_t)b * C_ * HW_ + hw;
#pragma unroll 4
    for (int c = 0; c < 64; c++) {
        float v = __ldg(xp + (size_t)c * HW_);
#pragma unroll
        for (int j = 0; j < 18; j++) acc[j] = fmaf(v, sw[j * 64 + c], acc[j]);
    }
    float* op = g_off + (size_t)b * 18 * HW_ + hw;
#pragma unroll
    for (int j = 0; j < 18; j++) op[(size_t)j * HW_] = acc[j];
}

// ---------------------------------------------------------------------------
// Kernel 3: weights -> bf16 split hi/lo, XOR-swizzled rows [o][c]:
// byte offset within 8KB tile = o*128 + ((c>>3)^(o&7))*16 + (c&7)*2
// ---------------------------------------------------------------------------
__global__ void k_reorder_w(const float* __restrict__ w) {
    int i = blockIdx.x * 256 + threadIdx.x;          // over 9*64*64
    if (i >= K2_ * O_ * C_) return;
    int c = i & 63;
    int r = i >> 6;
    int o = r & 63;
    int k = r >> 6;
    float v = w[((size_t)o * 64 + c) * 9 + k];
    __nv_bfloat16 hi = __float2bfloat16(v);
    float res = v - __bfloat162float(hi);
    __nv_bfloat16 lo = __float2bfloat16(res);
    int idx = o * 64 + ((((c >> 3) ^ (o & 7)) << 3)) + (c & 7);
    g_wbh[k * 4096 + idx] = hi;
    g_wbl[k * 4096 + idx] = lo;
}

// ---------------------------------------------------------------------------
// Kernel 4: main deformable conv via mma.sync (HMMA bf16, split-2 precision).
// One CTA per (b, h): M=128 px, N=64 o, K=64 c per tap, 9 taps.
// Warp tile: 32 px x 32 o (2 m-tiles x 4 n-tiles of m16n8k16).
// ---------------------------------------------------------------------------
#define A_HI   0
#define A_LO   16384
#define B_HI   32768
#define B_LO   40960
#define S_OFF  49152
#define SMEM_SZ (S_OFF + 18 * 128 * 4)

__global__ void __launch_bounds__(256, 2) k_main(float* __restrict__ out) {
    extern __shared__ char smem[];
    uint32_t sb = smem_u32(smem);
    float* s_off = (float*)(smem + S_OFF);

    int t    = threadIdx.x;
    int lane = t & 31;
    int wid  = t >> 5;
    int h    = blockIdx.x & 127;
    int b    = blockIdx.x >> 7;

    // stage offsets for this row (coalesced)
    {
        const float* op = g_off + (size_t)b * 18 * HW_ + (size_t)h * W_;
        for (int i = t; i < 18 * 128; i += 256)
            s_off[i] = op[(size_t)(i >> 7) * HW_ + (i & 127)];
    }

    float acc[2][4][4];
#pragma unroll
    for (int mi = 0; mi < 2; mi++)
#pragma unroll
        for (int nt = 0; nt < 4; nt++)
#pragma unroll
            for (int j = 0; j < 4; j++) acc[mi][nt][j] = 0.0f;

    // Phase-A mapping
    const int pa_cq = t & 15;    // float4 channel chunk 0..15
    const int pa_p0 = t >> 4;    // pixel within pass
    // Warp tile mapping
    const int wm = wid & 3;      // px group: 32*wm .. +31
    const int wn = wid >> 2;     // o  group: 32*wn .. +31
    // ldmatrix lane roles
    const int a_r  = lane & 15;
    const int a_q  = lane >> 4;
    const int b_or = (lane & 7) + ((lane >> 4) << 3);
    const int b_qb = (lane >> 3) & 1;

    const float* xtb = g_xt + (size_t)b * HW_ * C_;

    __syncthreads();

    for (int k = 0; k < 9; k++) {
        __syncthreads();   // previous phase-B reads of A/B finished

        // copy B_k hi/lo (pre-swizzled): 8KB each
        {
            const uint4* sh = (const uint4*)g_wbh + (size_t)k * 512;
            const uint4* sl = (const uint4*)g_wbl + (size_t)k * 512;
            uint4* dh = (uint4*)(smem + B_HI);
            uint4* dl = (uint4*)(smem + B_LO);
            dh[t]       = __ldg(sh + t);
            dh[t + 256] = __ldg(sh + t + 256);
            dl[t]       = __ldg(sl + t);
            dl[t + 256] = __ldg(sl + t + 256);
        }

        int kh = k / 3;
        int kw = k - kh * 3;

        // ---- Phase A: bilinear sampling -> bf16 hi/lo A tile (swizzled) ----
#pragma unroll 2
        for (int pass = 0; pass < 8; pass++) {
            int p = pass * 16 + pa_p0;
            float py = (float)(h - 1 + kh) + s_off[(2 * k) * 128 + p];
            float px = (float)(p - 1 + kw) + s_off[(2 * k + 1) * 128 + p];
            float fy0 = floorf(py), fx0 = floorf(px);
            float wy1 = py - fy0,   wx1 = px - fx0;
            float wy0 = 1.0f - wy1, wx0 = 1.0f - wx1;
            int y0 = (int)fy0, x0 = (int)fx0;
            int y1 = y0 + 1,   x1 = x0 + 1;
            bool vy0 = (unsigned)y0 < (unsigned)H_;
            bool vy1 = (unsigned)y1 < (unsigned)H_;
            bool vx0 = (unsigned)x0 < (unsigned)W_;
            bool vx1 = (unsigned)x1 < (unsigned)W_;
            int y0c = min(max(y0, 0), H_ - 1), y1c = min(max(y1, 0), H_ - 1);
            int x0c = min(max(x0, 0), W_ - 1), x1c = min(max(x1, 0), W_ - 1);
            float w00 = (vy0 && vx0) ? wy0 * wx0 : 0.0f;
            float w01 = (vy0 && vx1) ? wy0 * wx1 : 0.0f;
            float w10 = (vy1 && vx0) ? wy1 * wx0 : 0.0f;
            float w11 = (vy1 && vx1) ? wy1 * wx1 : 0.0f;

            const float4* r00 = (const float4*)(xtb + (size_t)(y0c * W_ + x0c) * C_) + pa_cq;
            const float4* r01 = (const float4*)(xtb + (size_t)(y0c * W_ + x1c) * C_) + pa_cq;
            const float4* r10 = (const float4*)(xtb + (size_t)(y1c * W_ + x0c) * C_) + pa_cq;
            const float4* r11 = (const float4*)(xtb + (size_t)(y1c * W_ + x1c) * C_) + pa_cq;
            float4 va = __ldg(r00);
            float4 vb = __ldg(r01);
            float4 vc = __ldg(r10);
            float4 vd = __ldg(r11);

            float4 s;
            s.x = w00 * va.x + w01 * vb.x + w10 * vc.x + w11 * vd.x;
            s.y = w00 * va.y + w01 * vb.y + w10 * vc.y + w11 * vd.y;
            s.z = w00 * va.z + w01 * vb.z + w10 * vc.z + w11 * vd.z;
            s.w = w00 * va.w + w01 * vb.w + w10 * vc.w + w11 * vd.w;

            // split to bf16 hi/lo (low bf16 = lower channel)
            uint32_t h0 = cvt2bf(s.y, s.x);
            uint32_t h1 = cvt2bf(s.w, s.z);
            float f0 = __uint_as_float(h0 << 16);
            float f1 = __uint_as_float(h0 & 0xFFFF0000u);
            float f2 = __uint_as_float(h1 << 16);
            float f3 = __uint_as_float(h1 & 0xFFFF0000u);
            uint32_t l0 = cvt2bf(s.y - f1, s.x - f0);
            uint32_t l1 = cvt2bf(s.w - f3, s.z - f2);

            int chunk = (pa_cq >> 1) ^ (p & 7);
            int off   = p * 128 + chunk * 16 + (pa_cq & 1) * 8;
            *(uint2*)(smem + A_HI + off) = make_uint2(h0, h1);
            *(uint2*)(smem + A_LO + off) = make_uint2(l0, l1);
        }
        __syncthreads();

        // ---- Phase B: HMMA over 4 k-tiles ----
#pragma unroll
        for (int kt = 0; kt < 4; kt++) {
            uint32_t ah[2][4], al[2][4];
#pragma unroll
            for (int mi = 0; mi < 2; mi++) {
                int row = wm * 32 + mi * 16 + a_r;
                uint32_t ad = sb + A_HI + row * 128 +
                              (((2 * kt + a_q) ^ (a_r & 7)) * 16);
                LDMX4(ah[mi], ad);
                LDMX4(al[mi], ad + (A_LO - A_HI));
            }
            uint32_t bh[2][4], bl[2][4];
#pragma unroll
            for (int j = 0; j < 2; j++) {
                int o = wn * 32 + j * 16 + b_or;
                uint32_t bd = sb + B_HI + o * 128 +
                              (((2 * kt + b_qb) ^ (o & 7)) * 16);
                LDMX4(bh[j], bd);
                LDMX4(bl[j], bd + (B_LO - B_HI));
            }
#pragma unroll
            for (int mi = 0; mi < 2; mi++) {
#pragma unroll
                for (int nt = 0; nt < 4; nt++) {
                    const uint32_t* bhp = &bh[nt >> 1][(nt & 1) * 2];
                    const uint32_t* blp = &bl[nt >> 1][(nt & 1) * 2];
                    MMA16816(acc[mi][nt], ah[mi], bhp[0], bhp[1]);
                    MMA16816(acc[mi][nt], al[mi], bhp[0], bhp[1]);
                    MMA16816(acc[mi][nt], ah[mi], blp[0], blp[1]);
                }
            }
        }
    }

    // ---- Epilogue: direct STG ----
    {
#pragma unroll
        for (int mi = 0; mi < 2; mi++) {
            int px = wm * 32 + mi * 16 + (lane >> 2);
#pragma unroll
            for (int nt = 0; nt < 4; nt++) {
                int o0 = wn * 32 + nt * 8 + 2 * (lane & 3);
                float* ob = out + ((size_t)(b * 64 + o0)) * HW_ + (size_t)h * W_;
                ob[px]           = acc[mi][nt][0];
                ob[HW_ + px]     = acc[mi][nt][1];
                ob[px + 8]       = acc[mi][nt][2];
                ob[HW_ + px + 8] = acc[mi][nt][3];
            }
        }
    }
}

// ---------------------------------------------------------------------------
extern "C" void kernel_launch(void* const* d_in, const int* in_sizes, int n_in,
                              void* d_out, int out_size) {
    const float* x     = (const float*)d_in[0];   // (8,64,128,128)
    const float* wght  = (const float*)d_in[1];   // (64,64,3,3)
    const float* w_off = (const float*)d_in[2];   // (18,64)
    const float* b_off = (const float*)d_in[3];   // (18,)
    float* out = (float*)d_out;                   // (8,64,128,128)

    k_transpose<<<dim3(HW_ / 32, C_ / 32, B_), dim3(32, 8)>>>(x);
    k_offsets<<<(B_ * HW_) / 256, 256>>>(x, w_off, b_off);
    k_reorder_w<<<(K2_ * O_ * C_ + 255) / 256, 256>>>(wght);

    cudaFuncSetAttribute(k_main, cudaFuncAttributeMaxDynamicSharedMemorySize,
                         SMEM_SZ);
    k_main<<<B_ * H_, 256, SMEM_SZ>>>(out);
}